// round 6
// baseline (speedup 1.0000x reference)
#include <cuda_runtime.h>
#include <cuda_bf16.h>

// Sbert idf-weighted masked mean pooling.
// hidden [B, L, D] f32, ids [B, L] i32, mask [B, L] i32, idf [V] f32
// out[b, d] = sum_l hidden[b,l,d] * (mask[b,l] ? idf[ids[b,l]] : 0) / max(sum_l mask[b,l], 1e-9)

constexpr int L = 100;
constexpr int D = 768;
constexpr int D4 = D / 4;        // 192 float4 lanes per row
constexpr int THREADS = D4;      // 192 threads: 1 float4 column group per thread

__global__ __launch_bounds__(THREADS) void sbert_pool_kernel(
    const float* __restrict__ hidden,
    const int*   __restrict__ ids,
    const int*   __restrict__ mask,
    const float* __restrict__ idf,
    float*       __restrict__ out)
{
    __shared__ float w[L];

    const int b = blockIdx.x;
    const int t = threadIdx.x;

    // Phase A: per-token weights into smem; mask count via syncthreads_count
    int m = 0;
    if (t < L) {
        const int base = b * L + t;
        m = mask[base];
        float wv = 0.0f;
        if (m) wv = idf[ids[base]];
        w[t] = wv;
    }
    const int cnt = __syncthreads_count(m != 0);   // full barrier + mask sum
    const float inv = 1.0f / fmaxf((float)cnt, 1e-9f);

    // Phase B: stream 100 rows of hidden, weighted accumulate
    const float4* __restrict__ hp =
        reinterpret_cast<const float4*>(hidden + (size_t)b * L * D) + t;

    float4 acc = make_float4(0.f, 0.f, 0.f, 0.f);
    #pragma unroll 5
    for (int l = 0; l < L; ++l) {
        const float4 h = hp[(size_t)l * D4];
        const float wv = w[l];
        acc.x = fmaf(h.x, wv, acc.x);
        acc.y = fmaf(h.y, wv, acc.y);
        acc.z = fmaf(h.z, wv, acc.z);
        acc.w = fmaf(h.w, wv, acc.w);
    }

    acc.x *= inv; acc.y *= inv; acc.z *= inv; acc.w *= inv;
    reinterpret_cast<float4*>(out + (size_t)b * D)[t] = acc;
}

extern "C" void kernel_launch(void* const* d_in, const int* in_sizes, int n_in,
                              void* d_out, int out_size) {
    const float* hidden = (const float*)d_in[0];
    const int*   ids    = (const int*)  d_in[1];
    const int*   mask   = (const int*)  d_in[2];
    const float* idf    = (const float*)d_in[3];
    float*       out    = (float*)d_out;

    const int B = out_size / D;   // 4096
    sbert_pool_kernel<<<B, THREADS>>>(hidden, ids, mask, idf, out);
}